// round 15
// baseline (speedup 1.0000x reference)
#include <cuda_runtime.h>
#include <cstdint>

// Problem constants
#define BB 4
#define LL 4096
#define DD 768
#define CHUNKS 512
#define ROWS 8             // LL / CHUNKS — fine chunks: 2048 blocks, smooth waves
#define KSPL 4             // gemv split-K factor
#define KS (DD / KSPL)     // 192 k-elements per slice
#define SPAN 16            // output rows per bcast block

// Scratch (device globals — zero-initialized at module load; bcast re-zeroes
// the accumulators at the end of every launch so each replay starts clean)
__device__ float g_hbar[BB][DD];              // UNNORMALIZED Σ exp(mask)·hs
__device__ float g_wtot[BB];                  // Σ exp(mask)
__device__ float g_ctx[BB][DD];               // final context row (bias folded)

// ---------------------------------------------------------------------------
// 1) wsum: each block computes its chunk's weighted partial in registers and
//    atomically accumulates it straight into g_hbar. Fine 8-row chunks give
//    ~14 blocks/SM -> high occupancy + smooth wave tail (vs 3.5 blocks/SM).
//    mask is {0,-1e9} => weights exactly {1,0}: dead rows skipped (uniform
//    branch); softmax normalization deferred to gemv via g_wtot.
// ---------------------------------------------------------------------------
__global__ void __launch_bounds__(192) wsum_kernel(const float* __restrict__ hs,
                                                   const float* __restrict__ mask) {
    const int t = threadIdx.x;                 // 192 = DD/4
    const int c = blockIdx.x;
    const int b = blockIdx.y;

    __shared__ float p[ROWS];
    if (t < ROWS) {                            // lanes 0..7 of warp 0
        float w = expf(__ldg(&mask[(size_t)b * LL + c * ROWS + t]));
        p[t] = w;
        #pragma unroll
        for (int o = 4; o > 0; o >>= 1) w += __shfl_down_sync(0x000000ffu, w, o, 8);
        if (t == 0) atomicAdd(&g_wtot[b], w);
    }
    __syncthreads();

    const float4* __restrict__ src =
        (const float4*)(hs + ((size_t)b * LL + (size_t)c * ROWS) * DD);

    float4 acc = make_float4(0.f, 0.f, 0.f, 0.f);
    #pragma unroll
    for (int r = 0; r < ROWS; r++) {
        const float pr = p[r];
        if (pr != 0.0f) {                      // uniform branch: skip dead rows
            const float4 x = src[(size_t)r * (DD / 4) + t];
            acc.x = fmaf(pr, x.x, acc.x);
            acc.y = fmaf(pr, x.y, acc.y);
            acc.z = fmaf(pr, x.z, acc.z);
            acc.w = fmaf(pr, x.w, acc.w);
        }
    }
    // Accumulate chunk partial into g_hbar (4 scalar REDs per thread,
    // 3072 distinct addresses -> spread-address RED throughput, no hotspot).
    float* __restrict__ h = g_hbar[b] + 4 * t;
    atomicAdd(h + 0, acc.x);
    atomicAdd(h + 1, acc.y);
    atomicAdd(h + 2, acc.z);
    atomicAdd(h + 3, acc.w);
}

// ---------------------------------------------------------------------------
// 2) gemv: ctx[b][d] = (hbar_unnorm[b,:]·Wv[d,:]) / wtot[b] + bv[d]
//    8 warps/block = 2 outputs x 4 k-slices; slice combine in smem.
//    Wv is L2-warm from the previous graph replay.
// ---------------------------------------------------------------------------
__global__ void __launch_bounds__(256) gemv_kernel(const float* __restrict__ Wv,
                                                   const float* __restrict__ bv) {
#if __CUDA_ARCH__ >= 900
    cudaGridDependencySynchronize();           // PDL: wait for wsum's atomics
#endif
    __shared__ float part[8];
    __shared__ float s_invw;
    const int w    = threadIdx.x >> 5;         // 0..7
    const int lane = threadIdx.x & 31;
    const int oidx = blockIdx.x * 2 + (w >> 2);  // 0..3071
    const int s    = w & 3;
    const int b    = oidx / DD, d = oidx % DD;

    if (threadIdx.x == 0) s_invw = 1.0f / g_wtot[blockIdx.x * 2 / DD];
    const float2* __restrict__ h2 = (const float2*)(g_hbar[b]) + s * (KS / 2);
    const float2* __restrict__ w2 = (const float2*)(Wv + (size_t)d * DD) + s * (KS / 2);

    float acc = 0.0f;
    #pragma unroll
    for (int i = 0; i < 3; i++) {              // KS/2 = 96 float2 over 32 lanes
        const float2 hv = h2[lane + 32 * i];
        const float2 wv = __ldg(&w2[lane + 32 * i]);
        acc = fmaf(hv.x, wv.x, fmaf(hv.y, wv.y, acc));
    }
    #pragma unroll
    for (int o = 16; o > 0; o >>= 1) acc += __shfl_down_sync(0xffffffffu, acc, o);
    if (lane == 0) part[w] = acc;
    __syncthreads();
    if (threadIdx.x < 2) {
        const int o2 = blockIdx.x * 2 + threadIdx.x;
        const float r = (part[threadIdx.x * 4] + part[threadIdx.x * 4 + 1] +
                         part[threadIdx.x * 4 + 2] + part[threadIdx.x * 4 + 3]) *
                        s_invw + __ldg(&bv[o2 % DD]);
        g_ctx[o2 / DD][o2 % DD] = r;
    }
}

// ---------------------------------------------------------------------------
// 3) bcast: out[b,l,:] = ctx[b,:] — measured-best config: scalar float4 STG,
//    16 rows/block, grid (256, BB); __stcs keeps output out of L2 residency.
//    Blocks with x==0 also re-zero the accumulators for the next replay
//    (safe: g_hbar/g_wtot are no longer read this launch; ctx is separate).
// ---------------------------------------------------------------------------
__global__ void __launch_bounds__(192) bcast_kernel(float* __restrict__ out) {
#if __CUDA_ARCH__ >= 900
    cudaGridDependencySynchronize();           // PDL: wait for gemv's writes
#endif
    const int b = blockIdx.y;
    const int t = threadIdx.x;                 // 192 = DD/4
    const float4 v = __ldg(&((const float4*)g_ctx[b])[t]);

    if (blockIdx.x == 0) {                     // reset accumulators for next replay
        ((float4*)g_hbar[b])[t] = make_float4(0.f, 0.f, 0.f, 0.f);
        if (t == 0) g_wtot[b] = 0.0f;
    }

    float4* __restrict__ dst =
        (float4*)(out + ((size_t)b * LL + (size_t)blockIdx.x * SPAN) * DD);
    #pragma unroll
    for (int r = 0; r < SPAN; r++)
        __stcs(&dst[(size_t)r * (DD / 4) + t], v);
}

// ---------------------------------------------------------------------------
// Launch helpers — PDL-attributed launches for the dependent kernels.
// ---------------------------------------------------------------------------
template <typename K, typename... Args>
static inline void launch_pdl(K kern, dim3 grid, dim3 block, Args... args) {
    cudaLaunchConfig_t cfg = {};
    cfg.gridDim = grid;
    cfg.blockDim = block;
    cudaLaunchAttribute attr[1];
    attr[0].id = cudaLaunchAttributeProgrammaticStreamSerialization;
    attr[0].val.programmaticStreamSerializationAllowed = 1;
    cfg.attrs = attr;
    cfg.numAttrs = 1;
    cudaLaunchKernelEx(&cfg, kern, args...);
}

// ---------------------------------------------------------------------------
// Inputs: hidden_states, attention_mask, Wq, bq, Wk, bk, Wv, bv (Q/K dead)
// ---------------------------------------------------------------------------
extern "C" void kernel_launch(void* const* d_in, const int* in_sizes, int n_in,
                              void* d_out, int out_size) {
    const float* hs   = (const float*)d_in[0];
    const float* mask = (const float*)d_in[1];
    const float* Wv   = (const float*)d_in[6];
    const float* bv   = (const float*)d_in[7];
    float* out = (float*)d_out;

    wsum_kernel<<<dim3(CHUNKS, BB), 192>>>(hs, mask);
    launch_pdl(gemv_kernel, dim3((BB * DD) / 2), dim3(256), Wv, bv);
    launch_pdl(bcast_kernel, dim3(LL / SPAN, BB), dim3(192), out);
}

// round 16
// speedup vs baseline: 2.0155x; 2.0155x over previous
#include <cuda_runtime.h>
#include <cstdint>

// Problem constants
#define BB 4
#define LL 4096
#define DD 768
#define CHUNKS 128
#define ROWS 32            // LL / CHUNKS
#define KSPL 4             // gemv split-K factor
#define KS (DD / KSPL)     // 192 k-elements per slice
#define SPAN 16            // output rows per bcast block

// Scratch (device globals — zero-initialized at module load; bcast re-zeroes
// the accumulators at the end of every launch so each replay starts clean)
__device__ float g_hbar[BB][DD];              // UNNORMALIZED Σ exp(mask)·hs
__device__ float g_wtot[BB];                  // Σ exp(mask)
__device__ float g_ctx[BB][DD];               // final context row (bias folded)

// ---------------------------------------------------------------------------
// 1) wsum: each block computes its chunk's weighted partial in registers and
//    atomically accumulates it straight into g_hbar. CHUNKS=128 (512 blocks):
//    512 atomic hits per address — below the L2 atomic serialization knee
//    (2048 hits at CHUNKS=512 measured 2.7x slower; reverted).
//    mask is {0,-1e9} => weights exactly {1,0}: dead rows skipped (uniform
//    branch); softmax normalization deferred to gemv via g_wtot.
// ---------------------------------------------------------------------------
__global__ void __launch_bounds__(192) wsum_kernel(const float* __restrict__ hs,
                                                   const float* __restrict__ mask) {
    const int t = threadIdx.x;                 // 192 = DD/4
    const int c = blockIdx.x;
    const int b = blockIdx.y;

    __shared__ float p[ROWS];
    if (t < ROWS) {                            // warp 0
        float w = expf(__ldg(&mask[(size_t)b * LL + c * ROWS + t]));
        p[t] = w;
        #pragma unroll
        for (int o = 16; o > 0; o >>= 1) w += __shfl_down_sync(0xffffffffu, w, o);
        if (t == 0) atomicAdd(&g_wtot[b], w);
    }
    __syncthreads();

    const float4* __restrict__ src =
        (const float4*)(hs + ((size_t)b * LL + (size_t)c * ROWS) * DD);

    float4 acc = make_float4(0.f, 0.f, 0.f, 0.f);
    #pragma unroll 8
    for (int r = 0; r < ROWS; r++) {
        const float pr = p[r];
        if (pr != 0.0f) {                      // uniform branch: skip dead rows
            const float4 x = src[(size_t)r * (DD / 4) + t];
            acc.x = fmaf(pr, x.x, acc.x);
            acc.y = fmaf(pr, x.y, acc.y);
            acc.z = fmaf(pr, x.z, acc.z);
            acc.w = fmaf(pr, x.w, acc.w);
        }
    }
    // Accumulate chunk partial into g_hbar (4 scalar REDs per thread).
    float* __restrict__ h = g_hbar[b] + 4 * t;
    atomicAdd(h + 0, acc.x);
    atomicAdd(h + 1, acc.y);
    atomicAdd(h + 2, acc.z);
    atomicAdd(h + 3, acc.w);
}

// ---------------------------------------------------------------------------
// 2) gemv: ctx[b][d] = (hbar_unnorm[b,:]·Wv[d,:]) / wtot[b] + bv[d]
//    8 warps/block = 2 outputs x 4 k-slices; slice combine in smem.
//    PDL prologue overlap: Wv/bv loads (pure inputs, independent of wsum)
//    are issued BEFORE gridDependencySynchronize, hiding their latency
//    behind the predecessor's tail.
// ---------------------------------------------------------------------------
__global__ void __launch_bounds__(256) gemv_kernel(const float* __restrict__ Wv,
                                                   const float* __restrict__ bv) {
    __shared__ float part[8];
    const int w    = threadIdx.x >> 5;         // 0..7
    const int lane = threadIdx.x & 31;
    const int oidx = blockIdx.x * 2 + (w >> 2);  // 0..3071
    const int s    = w & 3;
    const int b    = oidx / DD, d = oidx % DD;

    // --- pre-sync: load Wv slice + bias into registers (inputs only) -------
    const float2* __restrict__ w2 = (const float2*)(Wv + (size_t)d * DD) + s * (KS / 2);
    const float2 wv0 = __ldg(&w2[lane]);
    const float2 wv1 = __ldg(&w2[lane + 32]);
    const float2 wv2 = __ldg(&w2[lane + 64]);
    const float  bvv = __ldg(&bv[d]);

#if __CUDA_ARCH__ >= 900
    cudaGridDependencySynchronize();           // PDL: wait for wsum's atomics
#endif

    // --- post-sync: hbar loads + dot product -------------------------------
    const float2* __restrict__ h2 = (const float2*)(g_hbar[b]) + s * (KS / 2);
    const float2 hv0 = h2[lane];
    const float2 hv1 = h2[lane + 32];
    const float2 hv2 = h2[lane + 64];

    float acc;
    acc = fmaf(hv0.x, wv0.x, hv0.y * wv0.y);
    acc = fmaf(hv1.x, wv1.x, fmaf(hv1.y, wv1.y, acc));
    acc = fmaf(hv2.x, wv2.x, fmaf(hv2.y, wv2.y, acc));
    #pragma unroll
    for (int o = 16; o > 0; o >>= 1) acc += __shfl_down_sync(0xffffffffu, acc, o);
    if (lane == 0) part[w] = acc + ((s == 0) ? 0.0f : 0.0f);
    __syncthreads();
    if (threadIdx.x < 2) {
        const int o2 = blockIdx.x * 2 + threadIdx.x;
        const float invw = 1.0f / g_wtot[o2 / DD];
        const float r = (part[threadIdx.x * 4] + part[threadIdx.x * 4 + 1] +
                         part[threadIdx.x * 4 + 2] + part[threadIdx.x * 4 + 3]) *
                        invw + __ldg(&bv[o2 % DD]);
        g_ctx[o2 / DD][o2 % DD] = r;
    }
    (void)bvv;  // bias applied by the final 2 threads above (bvv warms L1/L2)
}

// ---------------------------------------------------------------------------
// 3) bcast: out[b,l,:] = ctx[b,:] — measured-best config: scalar float4 STG,
//    16 rows/block, grid (256, BB); __stcs keeps output out of L2 residency.
//    Blocks with x==0 also re-zero the accumulators for the next replay
//    (safe: g_hbar/g_wtot are no longer read this launch; ctx is separate).
// ---------------------------------------------------------------------------
__global__ void __launch_bounds__(192) bcast_kernel(float* __restrict__ out) {
#if __CUDA_ARCH__ >= 900
    cudaGridDependencySynchronize();           // PDL: wait for gemv's writes
#endif
    const int b = blockIdx.y;
    const int t = threadIdx.x;                 // 192 = DD/4
    const float4 v = __ldg(&((const float4*)g_ctx[b])[t]);

    if (blockIdx.x == 0) {                     // reset accumulators for next replay
        ((float4*)g_hbar[b])[t] = make_float4(0.f, 0.f, 0.f, 0.f);
        if (t == 0) g_wtot[b] = 0.0f;
    }

    float4* __restrict__ dst =
        (float4*)(out + ((size_t)b * LL + (size_t)blockIdx.x * SPAN) * DD);
    #pragma unroll
    for (int r = 0; r < SPAN; r++)
        __stcs(&dst[(size_t)r * (DD / 4) + t], v);
}

// ---------------------------------------------------------------------------
// Launch helpers — PDL-attributed launches for the dependent kernels.
// ---------------------------------------------------------------------------
template <typename K, typename... Args>
static inline void launch_pdl(K kern, dim3 grid, dim3 block, Args... args) {
    cudaLaunchConfig_t cfg = {};
    cfg.gridDim = grid;
    cfg.blockDim = block;
    cudaLaunchAttribute attr[1];
    attr[0].id = cudaLaunchAttributeProgrammaticStreamSerialization;
    attr[0].val.programmaticStreamSerializationAllowed = 1;
    cfg.attrs = attr;
    cfg.numAttrs = 1;
    cudaLaunchKernelEx(&cfg, kern, args...);
}

// ---------------------------------------------------------------------------
// Inputs: hidden_states, attention_mask, Wq, bq, Wk, bk, Wv, bv (Q/K dead)
// ---------------------------------------------------------------------------
extern "C" void kernel_launch(void* const* d_in, const int* in_sizes, int n_in,
                              void* d_out, int out_size) {
    const float* hs   = (const float*)d_in[0];
    const float* mask = (const float*)d_in[1];
    const float* Wv   = (const float*)d_in[6];
    const float* bv   = (const float*)d_in[7];
    float* out = (float*)d_out;

    wsum_kernel<<<dim3(CHUNKS, BB), 192>>>(hs, mask);
    launch_pdl(gemv_kernel, dim3((BB * DD) / 2), dim3(256), Wv, bv);
    launch_pdl(bcast_kernel, dim3(LL / SPAN, BB), dim3(192), out);
}